// round 1
// baseline (speedup 1.0000x reference)
#include <cuda_runtime.h>
#include <math.h>

#define NN 8192
#define MAXNNZ 1900000

// ---------------- scratch (device globals; no allocation allowed) ----------
__device__ float g_d[NN];            // rsqrt(deg)
__device__ int   g_cnt[NN];
__device__ int   g_rowptr[NN + 1];
__device__ int   g_colidx[MAXNNZ];
__device__ float g_H0[NN * 256];
__device__ float g_X1[NN * 256];
__device__ float g_G1[NN * 384];
__device__ float g_ZS[NN * 384];     // cols 0..127 = z1 ; 128..383 = s1 pre-softmax
__device__ float g_S1[NN * 256];
__device__ float g_U [NN * 256];
__device__ float g_Wcat[256 * 384];
__device__ float g_bcat[384];
__device__ float g_xp1[256 * 128];
__device__ float g_A2 [256 * 256];
__device__ float g_T  [256 * 256];
__device__ float g_X2 [256 * 128];
__device__ float g_Z2 [256 * 128];
__device__ float g_S2p[256 * 64];
__device__ float g_S2 [256 * 64];
__device__ float g_V2 [256 * 64];
__device__ float g_xp2[64 * 128];
__device__ float g_A3 [64 * 64];
__device__ float g_X3 [64 * 128];
__device__ float g_Z3 [64 * 128];

// ---------------- degree count + rsqrt ----------------
__global__ void deg_kernel(const float* __restrict__ adj, int* __restrict__ cnt,
                           float* __restrict__ drs) {
    int row = blockIdx.x;
    int tid = threadIdx.x;
    const float4* a = (const float4*)(adj + (size_t)row * NN);
    int c = 0;
    for (int j = tid; j < NN / 4; j += 256) {
        float4 v = a[j];
        c += (v.x != 0.f) + (v.y != 0.f) + (v.z != 0.f) + (v.w != 0.f);
    }
    __shared__ int sm[256];
    sm[tid] = c;
    __syncthreads();
    for (int s = 128; s > 0; s >>= 1) {
        if (tid < s) sm[tid] += sm[tid + s];
        __syncthreads();
    }
    if (tid == 0) {
        cnt[row] = sm[0];
        drs[row] = rsqrtf((float)sm[0]);
    }
}

// ---------------- exclusive scan of 8192 counts (1 block, 1024 thr) --------
__global__ void scan_kernel(const int* __restrict__ cnt, int* __restrict__ rowptr) {
    __shared__ int part[1024];
    int tid = threadIdx.x;
    int base = tid * 8;
    int local[8];
    int s = 0;
#pragma unroll
    for (int i = 0; i < 8; i++) { local[i] = s; s += cnt[base + i]; }
    part[tid] = s;
    __syncthreads();
    for (int off = 1; off < 1024; off <<= 1) {
        int v = 0;
        if (tid >= off) v = part[tid - off];
        __syncthreads();
        if (tid >= off) part[tid] += v;
        __syncthreads();
    }
    int chunk = (tid > 0) ? part[tid - 1] : 0;
#pragma unroll
    for (int i = 0; i < 8; i++) rowptr[base + i] = chunk + local[i];
    if (tid == 1023) rowptr[NN] = part[1023];
}

// ---------------- CSR fill ----------------
__global__ void fill_csr(const float* __restrict__ adj, const int* __restrict__ rowptr,
                         int* __restrict__ colidx) {
    int row = blockIdx.x;
    __shared__ int cur;
    if (threadIdx.x == 0) cur = rowptr[row];
    __syncthreads();
    const float* ar = adj + (size_t)row * NN;
    for (int j = threadIdx.x; j < NN; j += blockDim.x) {
        if (ar[j] != 0.f) {
            int p = atomicAdd(&cur, 1);
            colidx[p] = j;
        }
    }
}

// ---------------- SpMM: out[r,:] = d_r * sum_j d_j * B[j,:] (+bias) --------
__global__ void spmm_kernel(const int* __restrict__ rowptr, const int* __restrict__ colidx,
                            const float* __restrict__ drs, const float* __restrict__ B,
                            float* __restrict__ out, const float* __restrict__ bias, int kw) {
    int row = blockIdx.x;
    int t = threadIdx.x;
    int s = rowptr[row], e = rowptr[row + 1];
    float acc = 0.f;
    int p = s;
    for (; p + 4 <= e; p += 4) {
        int j0 = colidx[p], j1 = colidx[p + 1], j2 = colidx[p + 2], j3 = colidx[p + 3];
        float w0 = drs[j0], w1 = drs[j1], w2 = drs[j2], w3 = drs[j3];
        float b0 = B[(size_t)j0 * kw + t];
        float b1 = B[(size_t)j1 * kw + t];
        float b2 = B[(size_t)j2 * kw + t];
        float b3 = B[(size_t)j3 * kw + t];
        acc += w0 * b0; acc += w1 * b1; acc += w2 * b2; acc += w3 * b3;
    }
    for (; p < e; p++) {
        int j = colidx[p];
        acc += drs[j] * B[(size_t)j * kw + t];
    }
    float r = drs[row] * acc;
    if (bias) r += bias[t];
    out[(size_t)row * kw + t] = r;
}

// ---------------- 128x128 tiled SGEMM (M%128==0, N%128==0, K%8==0) ---------
__global__ __launch_bounds__(256) void sgemm128(const float* __restrict__ A,
                                                const float* __restrict__ B,
                                                float* __restrict__ C,
                                                int M, int N, int K) {
    __shared__ float As[8][132];
    __shared__ float Bs[8][132];
    int tid = threadIdx.x;
    int bm = blockIdx.y * 128, bn = blockIdx.x * 128;
    int ty = tid >> 4, tx = tid & 15;
    float acc[8][8];
#pragma unroll
    for (int i = 0; i < 8; i++)
#pragma unroll
        for (int j = 0; j < 8; j++) acc[i][j] = 0.f;

    for (int k0 = 0; k0 < K; k0 += 8) {
#pragma unroll
        for (int i = 0; i < 4; i++) {
            int e = tid + i * 256;
            int r = e >> 3, c = e & 7;
            As[c][r] = A[(size_t)(bm + r) * K + k0 + c];
        }
#pragma unroll
        for (int i = 0; i < 4; i++) {
            int e = tid + i * 256;
            int c = e >> 7, n = e & 127;
            Bs[c][n] = B[(size_t)(k0 + c) * N + bn + n];
        }
        __syncthreads();
#pragma unroll
        for (int c = 0; c < 8; c++) {
            float ra[8], rb[8];
#pragma unroll
            for (int i = 0; i < 8; i++) ra[i] = As[c][ty * 8 + i];
#pragma unroll
            for (int j = 0; j < 8; j++) rb[j] = Bs[c][tx * 8 + j];
#pragma unroll
            for (int i = 0; i < 8; i++)
#pragma unroll
                for (int j = 0; j < 8; j++) acc[i][j] += ra[i] * rb[j];
        }
        __syncthreads();
    }
#pragma unroll
    for (int i = 0; i < 8; i++)
#pragma unroll
        for (int j = 0; j < 8; j++)
            C[(size_t)(bm + ty * 8 + i) * N + bn + tx * 8 + j] = acc[i][j];
}

// ---------------- row softmax ----------------
__global__ void softmax_rows(const float* __restrict__ in, int ldi, int off,
                             float* __restrict__ out, int ldo) {
    int row = blockIdx.x, t = threadIdx.x, w = blockDim.x;
    __shared__ float sm[384];
    float v = in[(size_t)row * ldi + off + t];
    sm[t] = v;
    __syncthreads();
    for (int s = w >> 1; s > 0; s >>= 1) {
        if (t < s) sm[t] = fmaxf(sm[t], sm[t + s]);
        __syncthreads();
    }
    float mx = sm[0];
    __syncthreads();
    float e = expf(v - mx);
    sm[t] = e;
    __syncthreads();
    for (int s = w >> 1; s > 0; s >>= 1) {
        if (t < s) sm[t] += sm[t + s];
        __syncthreads();
    }
    out[(size_t)row * ldo + t] = e / sm[0];
}

// ---------------- big transpose GEMM: C += S^T @ V (split-K, atomics) ------
// grid.x = a_dim/8, grid.y = ksplit, block = bk threads
__global__ void tgemm_kernel(const float* __restrict__ S, int lds,
                             const float* __restrict__ V, int ldv,
                             float* __restrict__ C, int ldc, int K) {
    int ag = blockIdx.x * 8;
    int kchunk = K / gridDim.y;
    int k0 = blockIdx.y * kchunk, k1 = k0 + kchunk;
    int t = threadIdx.x;
    float acc[8];
#pragma unroll
    for (int u = 0; u < 8; u++) acc[u] = 0.f;
#pragma unroll 4
    for (int k = k0; k < k1; k++) {
        float v = V[(size_t)k * ldv + t];
        const float* sp = S + (size_t)k * lds + ag;
#pragma unroll
        for (int u = 0; u < 8; u++) acc[u] += sp[u] * v;
    }
#pragma unroll
    for (int u = 0; u < 8; u++) atomicAdd(&C[(ag + u) * ldc + t], acc[u]);
}

__global__ void zero_kernel(float* p, int n) {
    int i = blockIdx.x * blockDim.x + threadIdx.x;
    if (i < n) p[i] = 0.f;
}

// ---------------- small dense GEMMs (one block per output row) -------------
__global__ void gemm_small(const float* __restrict__ A, int lda,
                           const float* __restrict__ B, int ldb,
                           float* __restrict__ C, int ldc, int K,
                           const float* __restrict__ bias) {
    int m = blockIdx.x, t = threadIdx.x;
    const float* a = A + (size_t)m * lda;
    float acc = 0.f;
#pragma unroll 8
    for (int k = 0; k < K; k++) acc += a[k] * B[(size_t)k * ldb + t];
    if (bias) acc += bias[t];
    C[(size_t)m * ldc + t] = acc;
}

// C[m,t] = sum_k A[k, m] * B[k, t]
__global__ void gemm_small_AT(const float* __restrict__ A, int lda,
                              const float* __restrict__ B, int ldb,
                              float* __restrict__ C, int ldc, int K) {
    int m = blockIdx.x, t = threadIdx.x;
    float acc = 0.f;
#pragma unroll 8
    for (int k = 0; k < K; k++) acc += A[(size_t)k * lda + m] * B[(size_t)k * ldb + t];
    C[(size_t)m * ldc + t] = acc;
}

// ---------------- pack [W_d11 | W_d12] and [b_d11 | b_d12] -----------------
__global__ void pack_wcat(const float* __restrict__ Wd11, const float* __restrict__ Wd12,
                          const float* __restrict__ bd11, const float* __restrict__ bd12,
                          float* __restrict__ Wcat, float* __restrict__ bcat) {
    int idx = blockIdx.x * blockDim.x + threadIdx.x;
    if (idx < 256 * 384) {
        int k = idx / 384, n = idx % 384;
        Wcat[idx] = (n < 128) ? Wd11[k * 128 + n] : Wd12[k * 256 + (n - 128)];
    }
    if (idx < 384) bcat[idx] = (idx < 128) ? bd11[idx] : bd12[idx - 128];
}

// ---------------- final: colsum(Z3) -> fc -> log_softmax -------------------
__global__ void final_kernel(const float* __restrict__ Z3, const float* __restrict__ Wfc,
                             const float* __restrict__ bfc, float* __restrict__ out) {
    __shared__ float xf[128];
    __shared__ float logits[10];
    __shared__ float red;
    int t = threadIdx.x;  // 128 threads
    float s = 0.f;
    for (int r = 0; r < 64; r++) s += Z3[r * 128 + t];
    xf[t] = s;
    __syncthreads();
    if (t < 10) {
        float a = bfc[t];
        for (int k = 0; k < 128; k++) a += xf[k] * Wfc[k * 10 + t];
        logits[t] = a;
    }
    __syncthreads();
    if (t == 0) {
        float mx = logits[0];
        for (int i = 1; i < 10; i++) mx = fmaxf(mx, logits[i]);
        float se = 0.f;
        for (int i = 0; i < 10; i++) se += expf(logits[i] - mx);
        red = mx + logf(se);
    }
    __syncthreads();
    if (t < 10) out[t] = logits[t] - red;
}

// ---------------------------------------------------------------------------
static void* sym(const void* s) {
    void* p = nullptr;
    cudaGetSymbolAddress(&p, s);
    return p;
}

extern "C" void kernel_launch(void* const* d_in, const int* in_sizes, int n_in,
                              void* d_out, int out_size) {
    const float* x      = (const float*)d_in[0];
    const float* adj    = (const float*)d_in[1];
    const float* W_gcn1 = (const float*)d_in[2];
    const float* b_gcn1 = (const float*)d_in[3];
    const float* W_d11  = (const float*)d_in[4];
    const float* b_d11  = (const float*)d_in[5];
    const float* W_d12  = (const float*)d_in[6];
    const float* b_d12  = (const float*)d_in[7];
    const float* W_gcn2 = (const float*)d_in[8];
    const float* b_gcn2 = (const float*)d_in[9];
    const float* W_d21  = (const float*)d_in[10];
    const float* b_d21  = (const float*)d_in[11];
    const float* W_d22  = (const float*)d_in[12];
    const float* b_d22  = (const float*)d_in[13];
    const float* W_gcn3 = (const float*)d_in[14];
    const float* b_gcn3 = (const float*)d_in[15];
    const float* W_d31  = (const float*)d_in[16];
    const float* b_d31  = (const float*)d_in[17];
    // d_in[18]=W_d32, d_in[19]=b_d32: s3 = softmax over a width-1 axis == 1.0 exactly -> unused
    const float* W_fc   = (const float*)d_in[20];
    const float* b_fc   = (const float*)d_in[21];
    float* out = (float*)d_out;

    float* dD   = (float*)sym(g_d);
    int*   dCnt = (int*)sym(g_cnt);
    int*   dRp  = (int*)sym(g_rowptr);
    int*   dCi  = (int*)sym(g_colidx);
    float* H0   = (float*)sym(g_H0);
    float* X1   = (float*)sym(g_X1);
    float* G1   = (float*)sym(g_G1);
    float* ZS   = (float*)sym(g_ZS);
    float* S1   = (float*)sym(g_S1);
    float* U    = (float*)sym(g_U);
    float* Wcat = (float*)sym(g_Wcat);
    float* bcat = (float*)sym(g_bcat);
    float* xp1  = (float*)sym(g_xp1);
    float* A2   = (float*)sym(g_A2);
    float* T    = (float*)sym(g_T);
    float* X2   = (float*)sym(g_X2);
    float* Z2   = (float*)sym(g_Z2);
    float* S2p  = (float*)sym(g_S2p);
    float* S2   = (float*)sym(g_S2);
    float* V2   = (float*)sym(g_V2);
    float* xp2  = (float*)sym(g_xp2);
    float* A3   = (float*)sym(g_A3);
    float* X3   = (float*)sym(g_X3);
    float* Z3   = (float*)sym(g_Z3);

    // ---- CSR build + degree normalization factors ----
    deg_kernel<<<NN, 256>>>(adj, dCnt, dD);
    scan_kernel<<<1, 1024>>>(dCnt, dRp);
    fill_csr<<<NN, 256>>>(adj, dRp, dCi);

    // ---- level 1 ----
    sgemm128<<<dim3(256 / 128, NN / 128), 256>>>(x, W_gcn1, H0, NN, 256, 784);
    spmm_kernel<<<NN, 256>>>(dRp, dCi, dD, H0, X1, b_gcn1, 256);

    pack_wcat<<<(256 * 384 + 255) / 256, 256>>>(W_d11, W_d12, b_d11, b_d12, Wcat, bcat);
    sgemm128<<<dim3(384 / 128, NN / 128), 256>>>(X1, Wcat, G1, NN, 384, 256);
    spmm_kernel<<<NN, 384>>>(dRp, dCi, dD, G1, ZS, bcat, 384);

    softmax_rows<<<NN, 256>>>(ZS, 384, 128, S1, 256);     // s1
    spmm_kernel<<<NN, 256>>>(dRp, dCi, dD, S1, U, nullptr, 256);  // U = adj_n @ s1

    zero_kernel<<<(256 * 128 + 255) / 256, 256>>>(xp1, 256 * 128);
    zero_kernel<<<(256 * 256 + 255) / 256, 256>>>(A2, 256 * 256);
    tgemm_kernel<<<dim3(32, 32), 128>>>(S1, 256, ZS, 384, xp1, 128, NN);  // s1^T @ z1
    tgemm_kernel<<<dim3(32, 32), 256>>>(S1, 256, U, 256, A2, 256, NN);    // s1^T @ U

    // ---- level 2 (256 nodes) ----
    gemm_small<<<256, 128>>>(xp1, 128, W_gcn2, 128, T, 128, 128, nullptr);
    gemm_small<<<256, 128>>>(A2, 256, T, 128, X2, 128, 256, b_gcn2);
    gemm_small<<<256, 128>>>(X2, 128, W_d21, 128, T, 128, 128, nullptr);
    gemm_small<<<256, 128>>>(A2, 256, T, 128, Z2, 128, 256, b_d21);
    gemm_small<<<256, 64>>>(X2, 128, W_d22, 64, T, 64, 128, nullptr);
    gemm_small<<<256, 64>>>(A2, 256, T, 64, S2p, 64, 256, b_d22);
    softmax_rows<<<256, 64>>>(S2p, 64, 0, S2, 64);
    gemm_small_AT<<<64, 128>>>(S2, 64, Z2, 128, xp2, 128, 256);   // xp2 = S2^T @ Z2
    gemm_small<<<256, 64>>>(A2, 256, S2, 64, V2, 64, 256, nullptr); // V2 = A2 @ S2
    gemm_small_AT<<<64, 64>>>(S2, 64, V2, 64, A3, 64, 256);        // A3 = S2^T @ V2

    // ---- level 3 (64 nodes) ----
    gemm_small<<<64, 128>>>(xp2, 128, W_gcn3, 128, T, 128, 128, nullptr);
    gemm_small<<<64, 128>>>(A3, 64, T, 128, X3, 128, 64, b_gcn3);
    gemm_small<<<64, 128>>>(X3, 128, W_d31, 128, T, 128, 128, nullptr);
    gemm_small<<<64, 128>>>(A3, 64, T, 128, Z3, 128, 64, b_d31);

    // s3 == ones -> final = colsum(Z3) @ W_fc + b_fc -> log_softmax
    final_kernel<<<1, 128>>>(Z3, W_fc, b_fc, out);
}

// round 2
// speedup vs baseline: 1.1367x; 1.1367x over previous
#include <cuda_runtime.h>
#include <math.h>

#define NN 8192
#define ELLW 320

// ---------------- scratch (device globals; no allocation allowed) ----------
__device__ float g_d[NN];            // rsqrt(deg)
__device__ int   g_cnt[NN];
__device__ int   g_colidx[NN * ELLW];
__device__ float g_H0[NN * 256];
__device__ float g_X1[NN * 256];
__device__ float g_Y [NN * 256];
__device__ float g_ZS[NN * 384];     // cols 0..127 = z1 ; 128..383 = s1 pre-softmax
__device__ float g_S1[NN * 256];
__device__ float g_U [NN * 256];
__device__ float g_Wcat [256 * 384];
__device__ float g_bcat [384];
__device__ float g_Wcat2[128 * 192];
__device__ float g_bcat2[192];
__device__ float g_xp1[256 * 128];
__device__ float g_A2 [256 * 256];
__device__ float g_T  [256 * 256];
__device__ float g_X2 [256 * 128];
__device__ float g_ZS2[256 * 192];   // cols 0..127 = z2 ; 128..191 = s2 pre-softmax
__device__ float g_S2 [256 * 64];
__device__ float g_V2 [256 * 64];
__device__ float g_xp2[64 * 128];
__device__ float g_A3 [64 * 64];
__device__ float g_X3 [64 * 128];
__device__ float g_Z3 [64 * 128];

// ---------------- one-pass ELL build + degrees (deterministic) -------------
__global__ void ell_build(const float* __restrict__ adj, int* __restrict__ colidx,
                          int* __restrict__ cnt, float* __restrict__ drs) {
    int row = blockIdx.x;
    int tid = threadIdx.x, lane = tid & 31, w = tid >> 5;  // 8 warps, 1024 cols each
    const float* ar = adj + (size_t)row * NN;
    __shared__ int woff[9];
    int base = w * 1024;
    // phase 1: per-warp count
    int c = 0;
#pragma unroll 4
    for (int s = 0; s < 32; s++) {
        float v = ar[base + s * 32 + lane];
        c += (v != 0.f);
    }
    for (int o = 16; o > 0; o >>= 1) c += __shfl_down_sync(0xffffffffu, c, o);
    if (lane == 0) woff[w + 1] = c;
    __syncthreads();
    if (tid == 0) {
        woff[0] = 0;
        for (int i = 1; i <= 8; i++) woff[i] += woff[i - 1];
    }
    __syncthreads();
    // phase 2: ballot-compact (in-order => deterministic), 2nd read hits L1/L2
    int off = woff[w];
    unsigned ltmask = (1u << lane) - 1u;
    int* ci = colidx + (size_t)row * ELLW;
    for (int s = 0; s < 32; s++) {
        int col = base + s * 32 + lane;
        float v = ar[col];
        unsigned m = __ballot_sync(0xffffffffu, v != 0.f);
        if (v != 0.f) {
            int pos = off + __popc(m & ltmask);
            if (pos < ELLW) ci[pos] = col;
        }
        off += __popc(m);
    }
    if (tid == 0) {
        int tot = woff[8];
        cnt[row] = tot;
        drs[row] = rsqrtf((float)tot);
    }
}

// ---------------- SpMM (ELL): out[r,:] = d_r * sum_j d_j * B[j,:] (+bias) --
__global__ void spmm_ell(const int* __restrict__ colidx, const int* __restrict__ cnt,
                         const float* __restrict__ drs, const float* __restrict__ B,
                         float* __restrict__ out, const float* __restrict__ bias, int kw) {
    int row = blockIdx.x;
    int t = threadIdx.x;
    int e = cnt[row];
    if (e > ELLW) e = ELLW;
    const int* ci = colidx + (size_t)row * ELLW;
    float acc = 0.f;
    int p = 0;
    for (; p + 4 <= e; p += 4) {
        int j0 = ci[p], j1 = ci[p + 1], j2 = ci[p + 2], j3 = ci[p + 3];
        float w0 = drs[j0], w1 = drs[j1], w2 = drs[j2], w3 = drs[j3];
        float b0 = B[(size_t)j0 * kw + t];
        float b1 = B[(size_t)j1 * kw + t];
        float b2 = B[(size_t)j2 * kw + t];
        float b3 = B[(size_t)j3 * kw + t];
        acc += w0 * b0; acc += w1 * b1; acc += w2 * b2; acc += w3 * b3;
    }
    for (; p < e; p++) {
        int j = ci[p];
        acc += drs[j] * B[(size_t)j * kw + t];
    }
    float r = drs[row] * acc;
    if (bias) r += bias[t];
    out[(size_t)row * kw + t] = r;
}

// ---------------- 128x64 tiled SGEMM + optional bias ------------------------
// M%128==0, N%64==0, K%8==0. grid = (N/64, M/128), 256 threads, 8x4 micro.
__global__ __launch_bounds__(256) void sgemm_bias(const float* __restrict__ A,
                                                  const float* __restrict__ B,
                                                  float* __restrict__ C,
                                                  int M, int N, int K,
                                                  const float* __restrict__ bias) {
    __shared__ float As[8][132];
    __shared__ float Bs[8][68];
    int tid = threadIdx.x;
    int bm = blockIdx.y * 128, bn = blockIdx.x * 64;
    int ty = tid >> 4, tx = tid & 15;   // ty:0..15 (8 rows each), tx:0..15 (4 cols each)
    float acc[8][4];
#pragma unroll
    for (int i = 0; i < 8; i++)
#pragma unroll
        for (int j = 0; j < 4; j++) acc[i][j] = 0.f;

    for (int k0 = 0; k0 < K; k0 += 8) {
#pragma unroll
        for (int i = 0; i < 4; i++) {
            int e = tid + i * 256;
            int r = e >> 3, c = e & 7;
            As[c][r] = A[(size_t)(bm + r) * K + k0 + c];
        }
#pragma unroll
        for (int i = 0; i < 2; i++) {
            int e = tid + i * 256;
            int c = e >> 6, n = e & 63;
            Bs[c][n] = B[(size_t)(k0 + c) * N + bn + n];
        }
        __syncthreads();
#pragma unroll
        for (int c = 0; c < 8; c++) {
            float ra[8], rb[4];
#pragma unroll
            for (int i = 0; i < 8; i++) ra[i] = As[c][ty * 8 + i];
#pragma unroll
            for (int j = 0; j < 4; j++) rb[j] = Bs[c][tx * 4 + j];
#pragma unroll
            for (int i = 0; i < 8; i++)
#pragma unroll
                for (int j = 0; j < 4; j++) acc[i][j] += ra[i] * rb[j];
        }
        __syncthreads();
    }
    float bb[4];
#pragma unroll
    for (int j = 0; j < 4; j++) bb[j] = bias ? bias[bn + tx * 4 + j] : 0.f;
#pragma unroll
    for (int i = 0; i < 8; i++)
#pragma unroll
        for (int j = 0; j < 4; j++)
            C[(size_t)(bm + ty * 8 + i) * N + bn + tx * 4 + j] = acc[i][j] + bb[j];
}

// ---------------- row softmax ----------------
__global__ void softmax_rows(const float* __restrict__ in, int ldi, int off,
                             float* __restrict__ out, int ldo) {
    int row = blockIdx.x, t = threadIdx.x, w = blockDim.x;
    __shared__ float sm[384];
    float v = in[(size_t)row * ldi + off + t];
    sm[t] = v;
    __syncthreads();
    for (int s = w >> 1; s > 0; s >>= 1) {
        if (t < s) sm[t] = fmaxf(sm[t], sm[t + s]);
        __syncthreads();
    }
    float mx = sm[0];
    __syncthreads();
    float e = expf(v - mx);
    sm[t] = e;
    __syncthreads();
    for (int s = w >> 1; s > 0; s >>= 1) {
        if (t < s) sm[t] += sm[t + s];
        __syncthreads();
    }
    out[(size_t)row * ldo + t] = e / sm[0];
}

// ---------------- big transpose GEMM: C += S^T @ V (split-K, atomics) ------
__global__ void tgemm_kernel(const float* __restrict__ S, int lds,
                             const float* __restrict__ V, int ldv,
                             float* __restrict__ C, int ldc, int K) {
    int ag = blockIdx.x * 8;
    int kchunk = K / gridDim.y;
    int k0 = blockIdx.y * kchunk, k1 = k0 + kchunk;
    int t = threadIdx.x;
    float acc[8];
#pragma unroll
    for (int u = 0; u < 8; u++) acc[u] = 0.f;
#pragma unroll 4
    for (int k = k0; k < k1; k++) {
        float v = V[(size_t)k * ldv + t];
        const float* sp = S + (size_t)k * lds + ag;
#pragma unroll
        for (int u = 0; u < 8; u++) acc[u] += sp[u] * v;
    }
#pragma unroll
    for (int u = 0; u < 8; u++) atomicAdd(&C[(ag + u) * ldc + t], acc[u]);
}

__global__ void zero2_kernel(float* a, int na, float* b, int nb) {
    int i = blockIdx.x * blockDim.x + threadIdx.x;
    if (i < na) a[i] = 0.f;
    else if (i < na + nb) b[i - na] = 0.f;
}

// ---------------- small dense GEMMs (one block per output row) -------------
__global__ void gemm_small(const float* __restrict__ A, int lda,
                           const float* __restrict__ B, int ldb,
                           float* __restrict__ C, int ldc, int K,
                           const float* __restrict__ bias) {
    int m = blockIdx.x, t = threadIdx.x;
    const float* a = A + (size_t)m * lda;
    float acc = 0.f;
#pragma unroll 8
    for (int k = 0; k < K; k++) acc += a[k] * B[(size_t)k * ldb + t];
    if (bias) acc += bias[t];
    C[(size_t)m * ldc + t] = acc;
}

// C[m,t] = sum_k A[k, m] * B[k, t]
__global__ void gemm_small_AT(const float* __restrict__ A, int lda,
                              const float* __restrict__ B, int ldb,
                              float* __restrict__ C, int ldc, int K) {
    int m = blockIdx.x, t = threadIdx.x;
    float acc = 0.f;
#pragma unroll 8
    for (int k = 0; k < K; k++) acc += A[(size_t)k * lda + m] * B[(size_t)k * ldb + t];
    C[(size_t)m * ldc + t] = acc;
}

// ---------------- pack [W_d11 | W_d12] and [W_d21 | W_d22] ------------------
__global__ void pack_wcat(const float* __restrict__ Wd11, const float* __restrict__ Wd12,
                          const float* __restrict__ bd11, const float* __restrict__ bd12,
                          float* __restrict__ Wcat, float* __restrict__ bcat) {
    int idx = blockIdx.x * blockDim.x + threadIdx.x;
    if (idx < 256 * 384) {
        int k = idx / 384, n = idx % 384;
        Wcat[idx] = (n < 128) ? Wd11[k * 128 + n] : Wd12[k * 256 + (n - 128)];
    }
    if (idx < 384) bcat[idx] = (idx < 128) ? bd11[idx] : bd12[idx - 128];
}

__global__ void pack_wcat2(const float* __restrict__ Wd21, const float* __restrict__ Wd22,
                           const float* __restrict__ bd21, const float* __restrict__ bd22,
                           float* __restrict__ Wcat, float* __restrict__ bcat) {
    int idx = blockIdx.x * blockDim.x + threadIdx.x;
    if (idx < 128 * 192) {
        int k = idx / 192, n = idx % 192;
        Wcat[idx] = (n < 128) ? Wd21[k * 128 + n] : Wd22[k * 64 + (n - 128)];
    }
    if (idx < 192) bcat[idx] = (idx < 128) ? bd21[idx] : bd22[idx - 128];
}

// ---------------- final: colsum(Z3) -> fc -> log_softmax -------------------
__global__ void final_kernel(const float* __restrict__ Z3, const float* __restrict__ Wfc,
                             const float* __restrict__ bfc, float* __restrict__ out) {
    __shared__ float xf[128];
    __shared__ float logits[10];
    __shared__ float red;
    int t = threadIdx.x;  // 128 threads
    float s = 0.f;
    for (int r = 0; r < 64; r++) s += Z3[r * 128 + t];
    xf[t] = s;
    __syncthreads();
    if (t < 10) {
        float a = bfc[t];
        for (int k = 0; k < 128; k++) a += xf[k] * Wfc[k * 10 + t];
        logits[t] = a;
    }
    __syncthreads();
    if (t == 0) {
        float mx = logits[0];
        for (int i = 1; i < 10; i++) mx = fmaxf(mx, logits[i]);
        float se = 0.f;
        for (int i = 0; i < 10; i++) se += expf(logits[i] - mx);
        red = mx + logf(se);
    }
    __syncthreads();
    if (t < 10) out[t] = logits[t] - red;
}

// ---------------------------------------------------------------------------
static void* sym(const void* s) {
    void* p = nullptr;
    cudaGetSymbolAddress(&p, s);
    return p;
}

extern "C" void kernel_launch(void* const* d_in, const int* in_sizes, int n_in,
                              void* d_out, int out_size) {
    const float* x      = (const float*)d_in[0];
    const float* adj    = (const float*)d_in[1];
    const float* W_gcn1 = (const float*)d_in[2];
    const float* b_gcn1 = (const float*)d_in[3];
    const float* W_d11  = (const float*)d_in[4];
    const float* b_d11  = (const float*)d_in[5];
    const float* W_d12  = (const float*)d_in[6];
    const float* b_d12  = (const float*)d_in[7];
    const float* W_gcn2 = (const float*)d_in[8];
    const float* b_gcn2 = (const float*)d_in[9];
    const float* W_d21  = (const float*)d_in[10];
    const float* b_d21  = (const float*)d_in[11];
    const float* W_d22  = (const float*)d_in[12];
    const float* b_d22  = (const float*)d_in[13];
    const float* W_gcn3 = (const float*)d_in[14];
    const float* b_gcn3 = (const float*)d_in[15];
    const float* W_d31  = (const float*)d_in[16];
    const float* b_d31  = (const float*)d_in[17];
    // d_in[18]=W_d32, d_in[19]=b_d32: softmax over width-1 axis == 1 exactly -> unused
    const float* W_fc   = (const float*)d_in[20];
    const float* b_fc   = (const float*)d_in[21];
    float* out = (float*)d_out;

    float* dD    = (float*)sym(g_d);
    int*   dCnt  = (int*)sym(g_cnt);
    int*   dCi   = (int*)sym(g_colidx);
    float* H0    = (float*)sym(g_H0);
    float* X1    = (float*)sym(g_X1);
    float* Y     = (float*)sym(g_Y);
    float* ZS    = (float*)sym(g_ZS);
    float* S1    = (float*)sym(g_S1);
    float* U     = (float*)sym(g_U);
    float* Wcat  = (float*)sym(g_Wcat);
    float* bcat  = (float*)sym(g_bcat);
    float* Wcat2 = (float*)sym(g_Wcat2);
    float* bcat2 = (float*)sym(g_bcat2);
    float* xp1   = (float*)sym(g_xp1);
    float* A2    = (float*)sym(g_A2);
    float* T     = (float*)sym(g_T);
    float* X2    = (float*)sym(g_X2);
    float* ZS2   = (float*)sym(g_ZS2);
    float* S2    = (float*)sym(g_S2);
    float* V2    = (float*)sym(g_V2);
    float* xp2   = (float*)sym(g_xp2);
    float* A3    = (float*)sym(g_A3);
    float* X3    = (float*)sym(g_X3);
    float* Z3    = (float*)sym(g_Z3);

    // ---- CSR(ELL) build + degree normalization factors (one adjacency pass)
    ell_build<<<NN, 256>>>(adj, dCi, dCnt, dD);

    // ---- level 1 ----
    // H0 = x @ W_gcn1
    sgemm_bias<<<dim3(256 / 64, NN / 128), 256>>>(x, W_gcn1, H0, NN, 256, 784, nullptr);
    // X1 = adj_n @ H0 + b_gcn1
    spmm_ell<<<NN, 256>>>(dCi, dCnt, dD, H0, X1, b_gcn1, 256);
    // Y = adj_n @ X1        (reassociation: adj@(X1@W) == (adj@X1)@W)
    spmm_ell<<<NN, 256>>>(dCi, dCnt, dD, X1, Y, nullptr, 256);

    pack_wcat<<<(256 * 384 + 255) / 256, 256>>>(W_d11, W_d12, b_d11, b_d12, Wcat, bcat);
    // ZS = Y @ [W_d11 | W_d12] + [b_d11 | b_d12]
    sgemm_bias<<<dim3(384 / 64, NN / 128), 256>>>(Y, Wcat, ZS, NN, 384, 256, bcat);

    softmax_rows<<<NN, 256>>>(ZS, 384, 128, S1, 256);           // s1
    spmm_ell<<<NN, 256>>>(dCi, dCnt, dD, S1, U, nullptr, 256);  // U = adj_n @ s1

    zero2_kernel<<<(256 * 128 + 256 * 256 + 255) / 256, 256>>>(xp1, 256 * 128, A2, 256 * 256);
    tgemm_kernel<<<dim3(32, 32), 128>>>(S1, 256, ZS, 384, xp1, 128, NN);  // s1^T @ z1
    tgemm_kernel<<<dim3(32, 32), 256>>>(S1, 256, U, 256, A2, 256, NN);    // s1^T @ U

    // ---- level 2 (256 nodes) ----
    pack_wcat2<<<(128 * 192 + 255) / 256, 256>>>(W_d21, W_d22, b_d21, b_d22, Wcat2, bcat2);
    gemm_small<<<256, 128>>>(xp1, 128, W_gcn2, 128, T, 128, 128, nullptr);
    gemm_small<<<256, 128>>>(A2, 256, T, 128, X2, 128, 256, b_gcn2);
    gemm_small<<<256, 192>>>(X2, 128, Wcat2, 192, T, 192, 128, nullptr);
    gemm_small<<<256, 192>>>(A2, 256, T, 192, ZS2, 192, 256, bcat2);       // [z2 | s2pre]
    softmax_rows<<<256, 64>>>(ZS2, 192, 128, S2, 64);
    gemm_small_AT<<<64, 128>>>(S2, 64, ZS2, 192, xp2, 128, 256);   // xp2 = S2^T @ z2
    gemm_small<<<256, 64>>>(A2, 256, S2, 64, V2, 64, 256, nullptr);  // V2 = A2 @ S2
    gemm_small_AT<<<64, 64>>>(S2, 64, V2, 64, A3, 64, 256);          // A3 = S2^T @ V2

    // ---- level 3 (64 nodes) ----
    gemm_small<<<64, 128>>>(xp2, 128, W_gcn3, 128, T, 128, 128, nullptr);
    gemm_small<<<64, 128>>>(A3, 64, T, 128, X3, 128, 64, b_gcn3);
    gemm_small<<<64, 128>>>(X3, 128, W_d31, 128, T, 128, 128, nullptr);
    gemm_small<<<64, 128>>>(A3, 64, T, 128, Z3, 128, 64, b_d31);

    // s3 == ones -> final = colsum(Z3) @ W_fc + b_fc -> log_softmax
    final_kernel<<<1, 128>>>(Z3, W_fc, b_fc, out);
}

// round 4
// speedup vs baseline: 1.6554x; 1.4563x over previous
#include <cuda_runtime.h>
#include <math.h>

#define NN 8192
#define ELLW 320

// ---------------- scratch (device globals; no allocation allowed) ----------
__device__ float g_d[NN];            // rsqrt(deg)
__device__ int   g_cnt[NN];
__device__ int   g_colidx[NN * ELLW];
__device__ float g_H0s[NN * 256];    // d_j * (x @ W_gcn1)[j]
__device__ float g_X1s[NN * 256];    // d_r * X1[r]
__device__ float g_Y [NN * 256];
__device__ float g_ZS[NN * 384];     // cols 0..127 = z1 ; 128..383 = s1 pre-softmax
__device__ float g_S1 [NN * 256];
__device__ float g_S1s[NN * 256];    // d_r * s1[r]
__device__ float g_U [NN * 256];
__device__ float g_Wcat [256 * 384];
__device__ float g_bcat [384];
__device__ float g_Wcat2[128 * 192];
__device__ float g_bcat2[192];
__device__ float g_xp1[256 * 128];
__device__ float g_A2 [256 * 256];
__device__ float g_T  [256 * 256];
__device__ float g_X2 [256 * 128];
__device__ float g_ZS2[256 * 192];   // cols 0..127 = z2 ; 128..191 = s2 pre-softmax
__device__ float g_S2 [256 * 64];
__device__ float g_V2 [256 * 64];
__device__ float g_xp2[64 * 128];
__device__ float g_A3 [64 * 64];
__device__ float g_X3 [64 * 128];
__device__ float g_Z3 [64 * 128];

// ---------------- one-pass ELL build + degrees (single adjacency read) -----
__global__ void ell_build(const float* __restrict__ adj, int* __restrict__ colidx,
                          int* __restrict__ cnt, float* __restrict__ drs) {
    int row = blockIdx.x;
    int tid = threadIdx.x, lane = tid & 31, w = tid >> 5;  // 8 warps, 1024 cols each
    const float* ar = adj + (size_t)row * NN;
    __shared__ int woff[9];
    int base = w * 1024;
    // single read: build per-thread occupancy bitmask over its 32 elements
    unsigned msk = 0;
#pragma unroll
    for (int s = 0; s < 32; s++) {
        float v = ar[base + s * 32 + lane];
        msk |= (v != 0.f) ? (1u << s) : 0u;
    }
    int c = __popc(msk);
    for (int o = 16; o > 0; o >>= 1) c += __shfl_down_sync(0xffffffffu, c, o);
    if (lane == 0) woff[w + 1] = c;
    __syncthreads();
    if (tid == 0) {
        woff[0] = 0;
        for (int i = 1; i <= 8; i++) woff[i] += woff[i - 1];
    }
    __syncthreads();
    // compact from registers (no re-read), deterministic column order
    int off = woff[w];
    unsigned ltmask = (1u << lane) - 1u;
    int* ci = colidx + (size_t)row * ELLW;
#pragma unroll
    for (int s = 0; s < 32; s++) {
        unsigned bit = (msk >> s) & 1u;
        unsigned m = __ballot_sync(0xffffffffu, bit);
        if (bit) {
            int pos = off + __popc(m & ltmask);
            if (pos < ELLW) ci[pos] = base + s * 32 + lane;
        }
        off += __popc(m);
    }
    if (tid == 0) {
        int tot = woff[8];
        cnt[row] = tot;
        drs[row] = rsqrtf((float)tot);
    }
}

// ---------------- SpMM v2: out[r,:] = d_r * sum_j Bs[j,:]  (Bs pre-scaled) -
// kw = 256 fixed (64 float4). 256 threads = 4 groups x 64; group g sums nnz
// p = g, g+4, g+8, ... with float4 gathers; cross-group smem reduction.
// mode 1: out = s*(s*acc + bias)   (bias applied inside the d_r scaling)
// mode 0: out = s*acc
__global__ __launch_bounds__(256) void spmm4(const int* __restrict__ colidx,
                                             const int* __restrict__ cnt,
                                             const float* __restrict__ drs,
                                             const float4* __restrict__ B,
                                             float4* __restrict__ out,
                                             const float4* __restrict__ bias,
                                             int mode) {
    __shared__ int sidx[ELLW];
    __shared__ float4 sred[192];
    int row = blockIdx.x;
    int tid = threadIdx.x;
    int g = tid >> 6, c = tid & 63;
    int e = cnt[row];
    if (e > ELLW) e = ELLW;
    for (int i = tid; i < e; i += 256) sidx[i] = colidx[(size_t)row * ELLW + i];
    __syncthreads();

    float4 acc = make_float4(0.f, 0.f, 0.f, 0.f);
    int p = g;
    for (; p + 8 <= e; p += 8) {
        int j0 = sidx[p], j1 = sidx[p + 4];
        float4 v0 = B[(size_t)j0 * 64 + c];
        float4 v1 = B[(size_t)j1 * 64 + c];
        acc.x += v0.x; acc.y += v0.y; acc.z += v0.z; acc.w += v0.w;
        acc.x += v1.x; acc.y += v1.y; acc.z += v1.z; acc.w += v1.w;
    }
    for (; p < e; p += 4) {
        int j = sidx[p];
        float4 v = B[(size_t)j * 64 + c];
        acc.x += v.x; acc.y += v.y; acc.z += v.z; acc.w += v.w;
    }
    if (g > 0) sred[(g - 1) * 64 + c] = acc;
    __syncthreads();
    if (g == 0) {
        float4 a1 = sred[c], a2 = sred[64 + c], a3 = sred[128 + c];
        acc.x += a1.x + a2.x + a3.x;
        acc.y += a1.y + a2.y + a3.y;
        acc.z += a1.z + a2.z + a3.z;
        acc.w += a1.w + a2.w + a3.w;
        float s = drs[row];
        float4 r;
        if (mode) {
            float4 b = bias[c];
            r.x = s * (s * acc.x + b.x);
            r.y = s * (s * acc.y + b.y);
            r.z = s * (s * acc.z + b.z);
            r.w = s * (s * acc.w + b.w);
        } else {
            r.x = s * acc.x; r.y = s * acc.y; r.z = s * acc.z; r.w = s * acc.w;
        }
        out[(size_t)row * 64 + c] = r;
    }
}

// ---------------- 128x64 tiled SGEMM + optional bias + optional row scale --
__global__ __launch_bounds__(256) void sgemm_bias(const float* __restrict__ A,
                                                  const float* __restrict__ B,
                                                  float* __restrict__ C,
                                                  int M, int N, int K,
                                                  const float* __restrict__ bias,
                                                  const float* __restrict__ rowscale) {
    __shared__ float As[8][132];
    __shared__ float Bs[8][68];
    int tid = threadIdx.x;
    int bm = blockIdx.y * 128, bn = blockIdx.x * 64;
    int ty = tid >> 4, tx = tid & 15;
    float acc[8][4];
#pragma unroll
    for (int i = 0; i < 8; i++)
#pragma unroll
        for (int j = 0; j < 4; j++) acc[i][j] = 0.f;

    for (int k0 = 0; k0 < K; k0 += 8) {
#pragma unroll
        for (int i = 0; i < 4; i++) {
            int e = tid + i * 256;
            int r = e >> 3, c = e & 7;
            As[c][r] = A[(size_t)(bm + r) * K + k0 + c];
        }
#pragma unroll
        for (int i = 0; i < 2; i++) {
            int e = tid + i * 256;
            int c = e >> 6, n = e & 63;
            Bs[c][n] = B[(size_t)(k0 + c) * N + bn + n];
        }
        __syncthreads();
#pragma unroll
        for (int c = 0; c < 8; c++) {
            float ra[8], rb[4];
#pragma unroll
            for (int i = 0; i < 8; i++) ra[i] = As[c][ty * 8 + i];
#pragma unroll
            for (int j = 0; j < 4; j++) rb[j] = Bs[c][tx * 4 + j];
#pragma unroll
            for (int i = 0; i < 8; i++)
#pragma unroll
                for (int j = 0; j < 4; j++) acc[i][j] += ra[i] * rb[j];
        }
        __syncthreads();
    }
    float bb[4];
#pragma unroll
    for (int j = 0; j < 4; j++) bb[j] = bias ? bias[bn + tx * 4 + j] : 0.f;
#pragma unroll
    for (int i = 0; i < 8; i++) {
        float sc = rowscale ? rowscale[bm + ty * 8 + i] : 1.f;
#pragma unroll
        for (int j = 0; j < 4; j++)
            C[(size_t)(bm + ty * 8 + i) * N + bn + tx * 4 + j] = sc * (acc[i][j] + bb[j]);
    }
}

// ---------------- row softmax (256 wide) with scaled+unscaled outputs ------
__global__ void softmax_dual(const float* __restrict__ in, int ldi, int off,
                             const float* __restrict__ drs,
                             float* __restrict__ out, float* __restrict__ outs) {
    int row = blockIdx.x, t = threadIdx.x;
    __shared__ float sm[8];
    float v = in[(size_t)row * ldi + off + t];
    float m = v;
    for (int o = 16; o > 0; o >>= 1) m = fmaxf(m, __shfl_xor_sync(0xffffffffu, m, o));
    if ((t & 31) == 0) sm[t >> 5] = m;
    __syncthreads();
    if (t < 8) {
        float mm = sm[t];
        for (int o = 4; o > 0; o >>= 1) mm = fmaxf(mm, __shfl_xor_sync(0xffu, mm, o));
        sm[t] = mm;
    }
    __syncthreads();
    float mx = sm[0];
    __syncthreads();
    float e = expf(v - mx);
    float s = e;
    for (int o = 16; o > 0; o >>= 1) s += __shfl_xor_sync(0xffffffffu, s, o);
    if ((t & 31) == 0) sm[t >> 5] = s;
    __syncthreads();
    if (t < 8) {
        float ss = sm[t];
        for (int o = 4; o > 0; o >>= 1) ss += __shfl_xor_sync(0xffu, ss, o);
        sm[t] = ss;
    }
    __syncthreads();
    float r = e / sm[0];
    out[(size_t)row * 256 + t] = r;
    outs[(size_t)row * 256 + t] = drs[row] * r;
}

// small softmax for level 2 (64 wide)
__global__ void softmax_small(const float* __restrict__ in, int ldi, int off,
                              float* __restrict__ out, int ldo) {
    int row = blockIdx.x, t = threadIdx.x;
    __shared__ float sm[2];
    float v = in[(size_t)row * ldi + off + t];
    float m = v;
    for (int o = 16; o > 0; o >>= 1) m = fmaxf(m, __shfl_xor_sync(0xffffffffu, m, o));
    if ((t & 31) == 0) sm[t >> 5] = m;
    __syncthreads();
    float mx = fmaxf(sm[0], sm[1]);
    float e = expf(v - mx);
    float s = e;
    for (int o = 16; o > 0; o >>= 1) s += __shfl_xor_sync(0xffffffffu, s, o);
    if ((t & 31) == 0) sm[t >> 5] = s;
    __syncthreads();
    out[(size_t)row * ldo + t] = e / (sm[0] + sm[1]);
}

// ---------------- transpose GEMM: C += S^T @ V (split-K, atomics, 16 cols) -
__global__ void tgemm_kernel(const float* __restrict__ S, int lds,
                             const float* __restrict__ V, int ldv,
                             float* __restrict__ C, int ldc, int K) {
    int ag = blockIdx.x * 16;
    int kchunk = K / gridDim.y;
    int k0 = blockIdx.y * kchunk, k1 = k0 + kchunk;
    int t = threadIdx.x;
    float acc[16];
#pragma unroll
    for (int u = 0; u < 16; u++) acc[u] = 0.f;
#pragma unroll 2
    for (int k = k0; k < k1; k++) {
        float v = V[(size_t)k * ldv + t];
        const float4* sp = (const float4*)(S + (size_t)k * lds + ag);
        float4 s0 = sp[0], s1 = sp[1], s2 = sp[2], s3 = sp[3];
        acc[0] += s0.x * v; acc[1] += s0.y * v; acc[2] += s0.z * v; acc[3] += s0.w * v;
        acc[4] += s1.x * v; acc[5] += s1.y * v; acc[6] += s1.z * v; acc[7] += s1.w * v;
        acc[8] += s2.x * v; acc[9] += s2.y * v; acc[10] += s2.z * v; acc[11] += s2.w * v;
        acc[12] += s3.x * v; acc[13] += s3.y * v; acc[14] += s3.z * v; acc[15] += s3.w * v;
    }
#pragma unroll
    for (int u = 0; u < 16; u++) atomicAdd(&C[(ag + u) * ldc + t], acc[u]);
}

__global__ void zero2_kernel(float* a, int na, float* b, int nb) {
    int i = blockIdx.x * blockDim.x + threadIdx.x;
    if (i < na) a[i] = 0.f;
    else if (i < na + nb) b[i - na] = 0.f;
}

// ---------------- small dense GEMMs (one block per output row) -------------
__global__ void gemm_small(const float* __restrict__ A, int lda,
                           const float* __restrict__ B, int ldb,
                           float* __restrict__ C, int ldc, int K,
                           const float* __restrict__ bias) {
    int m = blockIdx.x, t = threadIdx.x;
    const float* a = A + (size_t)m * lda;
    float acc = 0.f;
#pragma unroll 8
    for (int k = 0; k < K; k++) acc += a[k] * B[(size_t)k * ldb + t];
    if (bias) acc += bias[t];
    C[(size_t)m * ldc + t] = acc;
}

__global__ void gemm_small_AT(const float* __restrict__ A, int lda,
                              const float* __restrict__ B, int ldb,
                              float* __restrict__ C, int ldc, int K) {
    int m = blockIdx.x, t = threadIdx.x;
    float acc = 0.f;
#pragma unroll 8
    for (int k = 0; k < K; k++) acc += A[(size_t)k * lda + m] * B[(size_t)k * ldb + t];
    C[(size_t)m * ldc + t] = acc;
}

// ---------------- pack [W_d11 | W_d12] and [W_d21 | W_d22] ------------------
__global__ void pack_wcat(const float* __restrict__ Wd11, const float* __restrict__ Wd12,
                          const float* __restrict__ bd11, const float* __restrict__ bd12,
                          float* __restrict__ Wcat, float* __restrict__ bcat) {
    int idx = blockIdx.x * blockDim.x + threadIdx.x;
    if (idx < 256 * 384) {
        int k = idx / 384, n = idx % 384;
        Wcat[idx] = (n < 128) ? Wd11[k * 128 + n] : Wd12[k * 256 + (n - 128)];
    }
    if (idx < 384) bcat[idx] = (idx < 128) ? bd11[idx] : bd12[idx - 128];
}

__global__ void pack_wcat2(const float* __restrict__ Wd21, const float* __restrict__ Wd22,
                           const float* __restrict__ bd21, const float* __restrict__ bd22,
                           float* __restrict__ Wcat, float* __restrict__ bcat) {
    int idx = blockIdx.x * blockDim.x + threadIdx.x;
    if (idx < 128 * 192) {
        int k = idx / 192, n = idx % 192;
        Wcat[idx] = (n < 128) ? Wd21[k * 128 + n] : Wd22[k * 64 + (n - 128)];
    }
    if (idx < 192) bcat[idx] = (idx < 128) ? bd21[idx] : bd22[idx - 128];
}

// ---------------- final: colsum(Z3) -> fc -> log_softmax -------------------
__global__ void final_kernel(const float* __restrict__ Z3, const float* __restrict__ Wfc,
                             const float* __restrict__ bfc, float* __restrict__ out) {
    __shared__ float xf[128];
    __shared__ float logits[10];
    __shared__ float red;
    int t = threadIdx.x;
    float s = 0.f;
    for (int r = 0; r < 64; r++) s += Z3[r * 128 + t];
    xf[t] = s;
    __syncthreads();
    if (t < 10) {
        float a = bfc[t];
        for (int k = 0; k < 128; k++) a += xf[k] * Wfc[k * 10 + t];
        logits[t] = a;
    }
    __syncthreads();
    if (t == 0) {
        float mx = logits[0];
        for (int i = 1; i < 10; i++) mx = fmaxf(mx, logits[i]);
        float se = 0.f;
        for (int i = 0; i < 10; i++) se += expf(logits[i] - mx);
        red = mx + logf(se);
    }
    __syncthreads();
    if (t < 10) out[t] = logits[t] - red;
}

// ---------------------------------------------------------------------------
static void* sym(const void* s) {
    void* p = nullptr;
    cudaGetSymbolAddress(&p, s);
    return p;
}

extern "C" void kernel_launch(void* const* d_in, const int* in_sizes, int n_in,
                              void* d_out, int out_size) {
    const float* x      = (const float*)d_in[0];
    const float* adj    = (const float*)d_in[1];
    const float* W_gcn1 = (const float*)d_in[2];
    const float* b_gcn1 = (const float*)d_in[3];
    const float* W_d11  = (const float*)d_in[4];
    const float* b_d11  = (const float*)d_in[5];
    const float* W_d12  = (const float*)d_in[6];
    const float* b_d12  = (const float*)d_in[7];
    const float* W_gcn2 = (const float*)d_in[8];
    const float* b_gcn2 = (const float*)d_in[9];
    const float* W_d21  = (const float*)d_in[10];
    const float* b_d21  = (const float*)d_in[11];
    const float* W_d22  = (const float*)d_in[12];
    const float* b_d22  = (const float*)d_in[13];
    const float* W_gcn3 = (const float*)d_in[14];
    const float* b_gcn3 = (const float*)d_in[15];
    const float* W_d31  = (const float*)d_in[16];
    const float* b_d31  = (const float*)d_in[17];
    // d_in[18]=W_d32, d_in[19]=b_d32: softmax over width-1 axis == 1 exactly -> unused
    const float* W_fc   = (const float*)d_in[20];
    const float* b_fc   = (const float*)d_in[21];
    float* out = (float*)d_out;

    float* dD    = (float*)sym(g_d);
    int*   dCnt  = (int*)sym(g_cnt);
    int*   dCi   = (int*)sym(g_colidx);
    float* H0s   = (float*)sym(g_H0s);
    float* X1s   = (float*)sym(g_X1s);
    float* Y     = (float*)sym(g_Y);
    float* ZS    = (float*)sym(g_ZS);
    float* S1    = (float*)sym(g_S1);
    float* S1s   = (float*)sym(g_S1s);
    float* U     = (float*)sym(g_U);
    float* Wcat  = (float*)sym(g_Wcat);
    float* bcat  = (float*)sym(g_bcat);
    float* Wcat2 = (float*)sym(g_Wcat2);
    float* bcat2 = (float*)sym(g_bcat2);
    float* xp1   = (float*)sym(g_xp1);
    float* A2    = (float*)sym(g_A2);
    float* T     = (float*)sym(g_T);
    float* X2    = (float*)sym(g_X2);
    float* ZS2   = (float*)sym(g_ZS2);
    float* S2    = (float*)sym(g_S2);
    float* V2    = (float*)sym(g_V2);
    float* xp2   = (float*)sym(g_xp2);
    float* A3    = (float*)sym(g_A3);
    float* X3    = (float*)sym(g_X3);
    float* Z3    = (float*)sym(g_Z3);

    // ---- ELL build + degree factors (single adjacency pass) ----
    ell_build<<<NN, 256>>>(adj, dCi, dCnt, dD);

    // ---- level 1 ----
    // H0s = diag(d) @ (x @ W_gcn1)
    sgemm_bias<<<dim3(256 / 64, NN / 128), 256>>>(x, W_gcn1, H0s, NN, 256, 784, nullptr, dD);
    // X1s = diag(d) @ X1,  X1 = adj_n @ H0 + b   ==> X1s[r] = d_r*(d_r*sum H0s + b)
    spmm4<<<NN, 256>>>(dCi, dCnt, dD, (const float4*)H0s, (float4*)X1s,
                       (const float4*)b_gcn1, 1);
    // Y = adj_n @ X1 = d_r * sum X1s[j]
    spmm4<<<NN, 256>>>(dCi, dCnt, dD, (const float4*)X1s, (float4*)Y, nullptr, 0);

    pack_wcat<<<(256 * 384 + 255) / 256, 256>>>(W_d11, W_d12, b_d11, b_d12, Wcat, bcat);
    // ZS = Y @ [W_d11 | W_d12] + [b_d11 | b_d12]   (reassociation)
    sgemm_bias<<<dim3(384 / 64, NN / 128), 256>>>(Y, Wcat, ZS, NN, 384, 256, bcat, nullptr);

    softmax_dual<<<NN, 256>>>(ZS, 384, 128, dD, S1, S1s);        // s1 and d*s1
    // U = adj_n @ s1 = d_r * sum S1s[j]
    spmm4<<<NN, 256>>>(dCi, dCnt, dD, (const float4*)S1s, (float4*)U, nullptr, 0);

    zero2_kernel<<<(256 * 128 + 256 * 256 + 255) / 256, 256>>>(xp1, 256 * 128, A2, 256 * 256);
    // xp1 = s1^T @ z1 : 256 output rows -> grid.x = 256/16 = 16   (R3 bug: was 8)
    tgemm_kernel<<<dim3(16, 32), 128>>>(S1, 256, ZS, 384, xp1, 128, NN);
    tgemm_kernel<<<dim3(16, 32), 256>>>(S1, 256, U, 256, A2, 256, NN);    // s1^T @ U

    // ---- level 2 (256 nodes) ----
    pack_wcat2<<<(128 * 192 + 255) / 256, 256>>>(W_d21, W_d22, b_d21, b_d22, Wcat2, bcat2);
    gemm_small<<<256, 128>>>(xp1, 128, W_gcn2, 128, T, 128, 128, nullptr);
    gemm_small<<<256, 128>>>(A2, 256, T, 128, X2, 128, 256, b_gcn2);
    gemm_small<<<256, 192>>>(X2, 128, Wcat2, 192, T, 192, 128, nullptr);
    gemm_small<<<256, 192>>>(A2, 256, T, 192, ZS2, 192, 256, bcat2);       // [z2 | s2pre]
    softmax_small<<<256, 64>>>(ZS2, 192, 128, S2, 64);
    gemm_small_AT<<<64, 128>>>(S2, 64, ZS2, 192, xp2, 128, 256);     // xp2 = S2^T @ z2
    gemm_small<<<256, 64>>>(A2, 256, S2, 64, V2, 64, 256, nullptr);  // V2 = A2 @ S2
    gemm_small_AT<<<64, 64>>>(S2, 64, V2, 64, A3, 64, 256);          // A3 = S2^T @ V2

    // ---- level 3 (64 nodes) ----
    gemm_small<<<64, 128>>>(xp2, 128, W_gcn3, 128, T, 128, 128, nullptr);
    gemm_small<<<64, 128>>>(A3, 64, T, 128, X3, 128, 64, b_gcn3);
    gemm_small<<<64, 128>>>(X3, 128, W_d31, 128, T, 128, 128, nullptr);
    gemm_small<<<64, 128>>>(A3, 64, T, 128, Z3, 128, 64, b_d31);

    // s3 == ones -> final = colsum(Z3) @ W_fc + b_fc -> log_softmax
    final_kernel<<<1, 128>>>(Z3, W_fc, b_fc, out);
}